// round 13
// baseline (speedup 1.0000x reference)
#include <cuda_runtime.h>
#include <cuda_fp16.h>
#include <cstdint>

#define N_NODES 50000
#define N_EDGES 800000
#define DIM 128
#define HEADS 8
#define THREADS 512

// ---- node GEMM config (R12, unchanged) ----
#define NTILE_M 64
#define KTW_H 517                 // uint2 per k-tile for W
#define KTA_H 261                 // uint2 per k-tile for node A (64 rows)
#define NCS_STRIDE 132
#define SMEM_W_U2 (8 * KTW_H)     // 4136 uint2 = 33088 B
#define SMEM_NA_U2 (8 * KTA_H)    // 2088 uint2 = 16704 B
#define NODE_SMEM ((SMEM_W_U2 + SMEM_NA_U2) * 8)   // 49792 B
#define GRID 296

// ---- edge kernel config (128-edge tile, 32x32 warp tiles, fp16 Cs) ----
#define ETILE_M 128
#define EKTA 520                  // uint2 per k-tile for A (128 rows*4 + 8 pad; 16B-aligned ktiles)
#define SMEM_EA_U2 (8 * EKTA)     // 4160 uint2 = 33280 B
#define CS_H_STRIDE 136           // halves per Cs row (272 B, 16B aligned)
#define CS_BYTES (ETILE_M * CS_H_STRIDE * 2)       // 34816 B
#define EDGE_SMEM ((SMEM_W_U2 + SMEM_EA_U2) * 8 + CS_BYTES)  // 101184 B -> 2 CTAs/SM

// Scratch (allocation-free rule: __device__ globals)
__device__ float g_Q[N_NODES * DIM];
__device__ float g_K[N_NODES * DIM];
__device__ float g_V[N_NODES * DIM];
__device__ float g_z[N_NODES * HEADS];

// ---------------------------------------------------------------------------
// helpers
// ---------------------------------------------------------------------------
__device__ __forceinline__ uint32_t pack_h2(float lo, float hi) {
    __half2 h = __floats2half2_rn(lo, hi);   // .x -> low 16 bits
    return *reinterpret_cast<uint32_t*>(&h);
}

__device__ __forceinline__ void mma16(float c[4], uint32_t a0, uint32_t a1,
                                      uint32_t a2, uint32_t a3,
                                      uint32_t b0, uint32_t b1) {
    asm("mma.sync.aligned.m16n8k16.row.col.f32.f16.f16.f32 "
        "{%0,%1,%2,%3}, {%4,%5,%6,%7}, {%8,%9}, {%0,%1,%2,%3};\n"
        : "+f"(c[0]), "+f"(c[1]), "+f"(c[2]), "+f"(c[3])
        : "r"(a0), "r"(a1), "r"(a2), "r"(a3), "r"(b0), "r"(b1));
}

__device__ __forceinline__ void red_add_v4(float* p, float4 v) {
    asm volatile("red.global.add.v4.f32 [%0], {%1,%2,%3,%4};"
                 :: "l"(p), "f"(v.x), "f"(v.y), "f"(v.z), "f"(v.w));
}

__device__ __forceinline__ void red_add_f32(float* p, float v) {
    asm volatile("red.global.add.f32 [%0], %1;" :: "l"(p), "f"(v));
}

// Stage W[128][128] (row-major k x n) into fp16 fragment layout.
__device__ __forceinline__ void stage_W(uint2* Wp, const float* __restrict__ W) {
    int tid = threadIdx.x;
#pragma unroll 1
    for (int idx = tid; idx < 4096; idx += THREADS) {
        int n = idx & 127;
        int rest = idx >> 7;       // 0..31
        int tp = rest & 3;
        int kt = rest >> 2;        // 0..7
        int k0 = kt * 16 + tp * 2;
        uint32_t lo = pack_h2(W[k0 * DIM + n], W[(k0 + 1) * DIM + n]);
        uint32_t hi = pack_h2(W[(k0 + 8) * DIM + n], W[(k0 + 9) * DIM + n]);
        Wp[kt * KTW_H + n * 4 + tp] = make_uint2(lo, hi);
    }
}

// ---------------------------------------------------------------------------
// edge kernel: 128-edge tiles, 16 warps of 32x32, fp16 everywhere in smem
// ---------------------------------------------------------------------------
// Prefetch + pack: 2 units/thread; unit u: row r = idx>>3, ktile kt = idx&7.
__device__ __forceinline__ void prefetch_pack(uint2 cur[2][4],
                                              const float* __restrict__ E,
                                              int row0, int tid) {
#pragma unroll
    for (int u = 0; u < 2; ++u) {
        int idx = u * THREADS + tid;   // 0..1023
        int r = idx >> 3, kt = idx & 7;
        const float4* p = (const float4*)&E[(size_t)(row0 + r) * DIM + kt * 16];
        float4 v0 = __ldcs(p), v1 = __ldcs(p + 1);
        float4 v2 = __ldcs(p + 2), v3 = __ldcs(p + 3);
        cur[u][0] = make_uint2(pack_h2(v0.x, v0.y), pack_h2(v2.x, v2.y));
        cur[u][1] = make_uint2(pack_h2(v0.z, v0.w), pack_h2(v2.z, v2.w));
        cur[u][2] = make_uint2(pack_h2(v1.x, v1.y), pack_h2(v3.x, v3.y));
        cur[u][3] = make_uint2(pack_h2(v1.z, v1.w), pack_h2(v3.z, v3.w));
    }
}

__device__ __forceinline__ void store_packed(uint2* Ap, const uint2 cur[2][4],
                                             int tid) {
#pragma unroll
    for (int u = 0; u < 2; ++u) {
        int idx = u * THREADS + tid;
        int r = idx >> 3, kt = idx & 7;
        uint4* base = (uint4*)(Ap + kt * EKTA + r * 4);   // 16B aligned (EKTA even)
        base[0] = make_uint4(cur[u][0].x, cur[u][0].y, cur[u][1].x, cur[u][1].y);
        base[1] = make_uint4(cur[u][2].x, cur[u][2].y, cur[u][3].x, cur[u][3].y);
    }
}

// Warp mainloop: 32 rows x 32 cols, K=128 (8 k-tiles of 16)
__device__ __forceinline__ void mma_tile_e(const uint2* Ap, const uint2* Wp,
                                           int wm, int wn, int lane,
                                           float c[2][4][4]) {
#pragma unroll
    for (int kt = 0; kt < 8; ++kt) {
        const uint2* ak = Ap + kt * EKTA;
        const uint2* wk = Wp + kt * KTW_H;
        uint2 a00 = ak[wm * 4 + lane];
        uint2 a01 = ak[(wm + 8) * 4 + lane];
        uint2 a10 = ak[(wm + 16) * 4 + lane];
        uint2 a11 = ak[(wm + 24) * 4 + lane];
#pragma unroll
        for (int nf = 0; nf < 4; ++nf) {
            uint2 b = wk[(wn + nf * 8) * 4 + lane];
            mma16(c[0][nf], a00.x, a01.x, a00.y, a01.y, b.x, b.y);
            mma16(c[1][nf], a10.x, a11.x, a10.y, a11.y, b.x, b.y);
        }
    }
}

__global__ __launch_bounds__(THREADS, 2)
void gemm_edge(const float* __restrict__ Ein, const float* __restrict__ W,
               const float* __restrict__ bias, const int* __restrict__ src,
               const int* __restrict__ dst, float* __restrict__ hacc,
               float* __restrict__ eout) {
    extern __shared__ uint2 smem[];
    uint2* Wp = smem;
    uint2* Ap = smem + SMEM_W_U2;
    __half* Cs = (__half*)(smem + SMEM_W_U2 + SMEM_EA_U2);
    int tid = threadIdx.x, lane = tid & 31, warp = tid >> 5;
    int wm = (warp & 3) * 32, wn = (warp >> 2) * 32;
    int g = lane >> 2, t = lane & 3;

    stage_W(Wp, W);
    float4 be4 = *(const float4*)&bias[lane * 4];

    const int nTiles = N_EDGES / ETILE_M;   // 6250 exact
    int tile = blockIdx.x;
    uint2 cur[2][4];
    if (tile < nTiles) prefetch_pack(cur, Ein, tile * ETILE_M, tid);
    __syncthreads();

#pragma unroll 1
    for (; tile < nTiles; tile += gridDim.x) {
        store_packed(Ap, cur, tid);
        __syncthreads();                     // A published; prev-tile Cs reads done
        float c[2][4][4];
#pragma unroll
        for (int i = 0; i < 2; ++i)
#pragma unroll
            for (int j = 0; j < 4; ++j)
#pragma unroll
                for (int k = 0; k < 4; ++k) c[i][j][k] = 0.f;
        mma_tile_e(Ap, Wp, wm, wn, lane, c);
        // prefetch next tile: overlaps Cs-write + epilogue
        int nxt = tile + gridDim.x;
        if (nxt < nTiles) prefetch_pack(cur, Ein, nxt * ETILE_M, tid);
        // write C fragments to Cs (fp16, own rows; no pre-sync needed)
#pragma unroll
        for (int mf = 0; mf < 2; ++mf) {
            int rr = wm + mf * 16 + g;
#pragma unroll
            for (int nf = 0; nf < 4; ++nf) {
                int col = wn + nf * 8 + t * 2;
                *(uint32_t*)&Cs[rr * CS_H_STRIDE + col] =
                    pack_h2(c[mf][nf][0], c[mf][nf][1]);
                *(uint32_t*)&Cs[(rr + 8) * CS_H_STRIDE + col] =
                    pack_h2(c[mf][nf][2], c[mf][nf][3]);
            }
        }
        __syncthreads();                     // Cs published; all mma A-reads done

        // epilogue: each warp owns 8 edges; 2 at a time, loads batched
        int rbase = warp * 8;
        int ebase = tile * ETILE_M + rbase;
        int sn[8], dn[8];
#pragma unroll
        for (int i = 0; i < 8; ++i) {
            sn[i] = __ldg(&src[ebase + i]);
            dn[i] = __ldg(&dst[ebase + i]);
        }
#pragma unroll
        for (int i = 0; i < 8; i += 2) {
            float4 q0 = *(const float4*)&g_Q[(size_t)dn[i] * DIM + lane * 4];
            float4 k0 = *(const float4*)&g_K[(size_t)sn[i] * DIM + lane * 4];
            float4 v0 = *(const float4*)&g_V[(size_t)sn[i] * DIM + lane * 4];
            float4 q1 = *(const float4*)&g_Q[(size_t)dn[i + 1] * DIM + lane * 4];
            float4 k1 = *(const float4*)&g_K[(size_t)sn[i + 1] * DIM + lane * 4];
            float4 v1 = *(const float4*)&g_V[(size_t)sn[i + 1] * DIM + lane * 4];
            uint2 w0 = *(const uint2*)&Cs[(rbase + i) * CS_H_STRIDE + lane * 4];
            uint2 w1 = *(const uint2*)&Cs[(rbase + i + 1) * CS_H_STRIDE + lane * 4];
            float2 a0 = __half22float2(*(__half2*)&w0.x);
            float2 a1 = __half22float2(*(__half2*)&w0.y);
            float2 b0 = __half22float2(*(__half2*)&w1.x);
            float2 b1 = __half22float2(*(__half2*)&w1.y);
            float4 p0 = make_float4(a0.x + be4.x, a0.y + be4.y,
                                    a1.x + be4.z, a1.y + be4.w);
            float4 p1 = make_float4(b0.x + be4.x, b0.y + be4.y,
                                    b1.x + be4.z, b1.y + be4.w);

            float4 s0, s1;
            s0.x = q0.x * k0.x * 0.25f * p0.x;
            s0.y = q0.y * k0.y * 0.25f * p0.y;
            s0.z = q0.z * k0.z * 0.25f * p0.z;
            s0.w = q0.w * k0.w * 0.25f * p0.w;
            s1.x = q1.x * k1.x * 0.25f * p1.x;
            s1.y = q1.y * k1.y * 0.25f * p1.y;
            s1.z = q1.z * k1.z * 0.25f * p1.z;
            s1.w = q1.w * k1.w * 0.25f * p1.w;
            __stcs((float4*)&eout[(size_t)(ebase + i) * DIM + lane * 4], s0);
            __stcs((float4*)&eout[(size_t)(ebase + i + 1) * DIM + lane * 4], s1);

            float h0 = s0.x + s0.y + s0.z + s0.w;
            float h1 = s1.x + s1.y + s1.z + s1.w;
            h0 += __shfl_xor_sync(0xffffffffu, h0, 1);
            h0 += __shfl_xor_sync(0xffffffffu, h0, 2);
            h1 += __shfl_xor_sync(0xffffffffu, h1, 1);
            h1 += __shfl_xor_sync(0xffffffffu, h1, 2);
            float e0 = expf(fminf(fmaxf(h0, -5.f), 5.f));
            float e1 = expf(fminf(fmaxf(h1, -5.f), 5.f));

            red_add_v4(&hacc[(size_t)dn[i] * DIM + lane * 4],
                       make_float4(v0.x * e0, v0.y * e0, v0.z * e0, v0.w * e0));
            red_add_v4(&hacc[(size_t)dn[i + 1] * DIM + lane * 4],
                       make_float4(v1.x * e1, v1.y * e1, v1.z * e1, v1.w * e1));
            if ((lane & 3) == 0) {
                red_add_f32(&g_z[dn[i] * HEADS + (lane >> 2)], e0);
                red_add_f32(&g_z[dn[i + 1] * HEADS + (lane >> 2)], e1);
            }
        }
        // no sync: next iteration's post-store_A sync orders Cs reuse
    }
}

// ---------------------------------------------------------------------------
// node-GEMM path (fp16 mma.sync, R12 passing version)
// ---------------------------------------------------------------------------
template <bool STREAM>
__device__ __forceinline__ void prefetch_nA(float4 v[4], const float* __restrict__ A,
                                            int row0, int M, int tid) {
    int r = tid >> 3, kt = tid & 7;
    int grow = row0 + r;
    if (grow < M) {
        const float4* p = (const float4*)&A[(size_t)grow * DIM + kt * 16];
#pragma unroll
        for (int i = 0; i < 4; ++i) v[i] = STREAM ? __ldcs(p + i) : __ldg(p + i);
    } else {
#pragma unroll
        for (int i = 0; i < 4; ++i) v[i] = make_float4(0.f, 0.f, 0.f, 0.f);
    }
}

__device__ __forceinline__ void store_nA(uint2* Ap, const float4 v[4], int tid) {
    int r = tid >> 3, kt = tid & 7;
    uint2* base = Ap + kt * KTA_H + r * 4;
    base[0] = make_uint2(pack_h2(v[0].x, v[0].y), pack_h2(v[2].x, v[2].y));
    base[1] = make_uint2(pack_h2(v[0].z, v[0].w), pack_h2(v[2].z, v[2].w));
    base[2] = make_uint2(pack_h2(v[1].x, v[1].y), pack_h2(v[3].x, v[3].y));
    base[3] = make_uint2(pack_h2(v[1].z, v[1].w), pack_h2(v[3].z, v[3].w));
}

__global__ __launch_bounds__(THREADS, 2)
void gemm_node(const float* __restrict__ A,
               const float* __restrict__ W0, const float* __restrict__ W1,
               const float* __restrict__ W2, const float* __restrict__ B0,
               const float* __restrict__ B1, const float* __restrict__ B2,
               float* __restrict__ O0, float* __restrict__ O1,
               float* __restrict__ O2, int M) {
    extern __shared__ uint2 smem[];
    uint2* Wp = smem;
    uint2* Ap = smem + SMEM_W_U2;
    int which = blockIdx.y;
    const float* W = (which == 0) ? W0 : (which == 1) ? W1 : W2;
    const float* bias = (which == 0) ? B0 : (which == 1) ? B1 : B2;
    float* out = (which == 0) ? O0 : (which == 1) ? O1 : O2;

    int tid = threadIdx.x, lane = tid & 31, warp = tid >> 5;
    int wm = (warp & 3) * 16, wn = (warp >> 2) * 32;
    int g = lane >> 2, t = lane & 3;

    stage_W(Wp, W);
    float2 bias2[4];
#pragma unroll
    for (int nf = 0; nf < 4; ++nf)
        bias2[nf] = *(const float2*)&bias[wn + nf * 8 + t * 2];

    int nTiles = (M + NTILE_M - 1) / NTILE_M;
    int tile = blockIdx.x;
    float4 cur[4];
    if (tile < nTiles) prefetch_nA<false>(cur, A, tile * NTILE_M, M, tid);
    __syncthreads();

#pragma unroll 1
    for (; tile < nTiles; tile += gridDim.x) {
        store_nA(Ap, cur, tid);
        __syncthreads();
        int nxt = tile + gridDim.x;
        if (nxt < nTiles) prefetch_nA<false>(cur, A, nxt * NTILE_M, M, tid);
        float c[4][4];
#pragma unroll
        for (int j = 0; j < 4; ++j)
#pragma unroll
            for (int k = 0; k < 4; ++k) c[j][k] = 0.f;
#pragma unroll
        for (int kt = 0; kt < 8; ++kt) {
            const uint2* ak = Ap + kt * KTA_H;
            const uint2* wk = Wp + kt * KTW_H;
            uint2 aA = ak[wm * 4 + lane];
            uint2 aB = ak[(wm + 8) * 4 + lane];
#pragma unroll
            for (int nf = 0; nf < 4; ++nf) {
                uint2 b = wk[(wn + nf * 8) * 4 + lane];
                mma16(c[nf], aA.x, aB.x, aA.y, aB.y, b.x, b.y);
            }
        }
        __syncthreads();
        int r0 = tile * NTILE_M + wm + g;
#pragma unroll
        for (int nf = 0; nf < 4; ++nf) {
            int col = wn + nf * 8 + t * 2;
            if (r0 < M)
                *(float2*)&out[(size_t)r0 * DIM + col] =
                    make_float2(c[nf][0] + bias2[nf].x,
                                c[nf][1] + bias2[nf].y);
            if (r0 + 8 < M)
                *(float2*)&out[(size_t)(r0 + 8) * DIM + col] =
                    make_float2(c[nf][2] + bias2[nf].x,
                                c[nf][3] + bias2[nf].y);
        }
    }
}

// ---------------------------------------------------------------------------
// finalize: h_out = wV / (z + 1e-6)
// ---------------------------------------------------------------------------
__global__ void finalize_kernel(float* __restrict__ hacc) {
    int i = blockIdx.x * blockDim.x + threadIdx.x;
    if (i < N_NODES * DIM) {
        int node = i >> 7;
        int head = (i >> 4) & 7;
        hacc[i] = hacc[i] / (g_z[node * HEADS + head] + 1e-6f);
    }
}

// ---------------------------------------------------------------------------
// launch
// ---------------------------------------------------------------------------
extern "C" void kernel_launch(void* const* d_in, const int* in_sizes, int n_in,
                              void* d_out, int out_size) {
    const float* h  = (const float*)d_in[0];
    const float* e  = (const float*)d_in[1];
    const int*   src = (const int*)d_in[2];
    const int*   dst = (const int*)d_in[3];
    const float* Wq = (const float*)d_in[4];
    const float* bq = (const float*)d_in[5];
    const float* Wk = (const float*)d_in[6];
    const float* bk = (const float*)d_in[7];
    const float* Wv = (const float*)d_in[8];
    const float* bv = (const float*)d_in[9];
    const float* We = (const float*)d_in[10];
    const float* be = (const float*)d_in[11];

    float* out  = (float*)d_out;
    float* hacc = out;                               // [N,H,D] accumulator -> h_out
    float* eout = out + (size_t)N_NODES * DIM;       // [E,H,D] e_out

    float *qp, *kp, *vp, *zp;
    cudaGetSymbolAddress((void**)&qp, g_Q);
    cudaGetSymbolAddress((void**)&kp, g_K);
    cudaGetSymbolAddress((void**)&vp, g_V);
    cudaGetSymbolAddress((void**)&zp, g_z);

    cudaFuncSetAttribute(gemm_node, cudaFuncAttributeMaxDynamicSharedMemorySize, NODE_SMEM);
    cudaFuncSetAttribute(gemm_edge, cudaFuncAttributeMaxDynamicSharedMemorySize, EDGE_SMEM);

    cudaMemsetAsync(hacc, 0, (size_t)N_NODES * DIM * sizeof(float));
    cudaMemsetAsync(zp, 0, (size_t)N_NODES * HEADS * sizeof(float));

    dim3 ngrid(GRID, 3);
    gemm_node<<<ngrid, THREADS, NODE_SMEM>>>(h, Wq, Wk, Wv, bq, bk, bv,
                                             qp, kp, vp, N_NODES);
    gemm_edge<<<GRID, THREADS, EDGE_SMEM>>>(e, We, be, src, dst, hacc, eout);
    finalize_kernel<<<(N_NODES * DIM + 255) / 256, 256>>>(hacc);
}

// round 14
// speedup vs baseline: 1.3911x; 1.3911x over previous
#include <cuda_runtime.h>
#include <cuda_fp16.h>
#include <cstdint>

#define N_NODES 50000
#define N_EDGES 800000
#define DIM 128
#define HEADS 8
#define TILE_M 64
#define THREADS 512
#define KTW_H 517                 // uint2 per k-tile for W (128 n * 4 + 5 pad)
#define KTA_H 261                 // uint2 per k-tile for A (64 rows * 4 + 5 pad)
#define CS_H_STRIDE 136           // halves per Cs row (272 B, 8B-aligned lane reads)
#define SMEM_W_U2 (8 * KTW_H)     // 4136 uint2 = 33088 B
#define SMEM_A_U2 (8 * KTA_H)     // 2088 uint2 = 16704 B
#define NODE_SMEM ((SMEM_W_U2 + SMEM_A_U2) * 8)             // 49792 B
#define EDGE_SMEM (NODE_SMEM + TILE_M * CS_H_STRIDE * 2)    // 67200 B -> 2 CTAs/SM
#define GRID 296

// Scratch (allocation-free rule: __device__ globals) — fp16 halves gather bytes
__device__ __half g_Q[N_NODES * DIM];
__device__ __half g_K[N_NODES * DIM];
__device__ __half g_V[N_NODES * DIM];
__device__ float  g_z[N_NODES * HEADS];

// ---------------------------------------------------------------------------
// helpers
// ---------------------------------------------------------------------------
__device__ __forceinline__ uint32_t pack_h2(float lo, float hi) {
    __half2 h = __floats2half2_rn(lo, hi);   // .x -> low 16 bits
    return *reinterpret_cast<uint32_t*>(&h);
}

__device__ __forceinline__ float4 unpack_h4(uint2 w) {
    float2 a = __half22float2(*reinterpret_cast<__half2*>(&w.x));
    float2 b = __half22float2(*reinterpret_cast<__half2*>(&w.y));
    return make_float4(a.x, a.y, b.x, b.y);
}

// m16n8k16 f16 mma, f32 accumulate.
__device__ __forceinline__ void mma16(float c[4], uint32_t a0, uint32_t a1,
                                      uint32_t a2, uint32_t a3,
                                      uint32_t b0, uint32_t b1) {
    asm("mma.sync.aligned.m16n8k16.row.col.f32.f16.f16.f32 "
        "{%0,%1,%2,%3}, {%4,%5,%6,%7}, {%8,%9}, {%0,%1,%2,%3};\n"
        : "+f"(c[0]), "+f"(c[1]), "+f"(c[2]), "+f"(c[3])
        : "r"(a0), "r"(a1), "r"(a2), "r"(a3), "r"(b0), "r"(b1));
}

__device__ __forceinline__ void red_add_v4(float* p, float4 v) {
    asm volatile("red.global.add.v4.f32 [%0], {%1,%2,%3,%4};"
                 :: "l"(p), "f"(v.x), "f"(v.y), "f"(v.z), "f"(v.w));
}

__device__ __forceinline__ void red_add_f32(float* p, float v) {
    asm volatile("red.global.add.f32 [%0], %1;" :: "l"(p), "f"(v));
}

// Stage W[128][128] (row-major k x n) into fp16 fragment layout.
__device__ __forceinline__ void stage_W(uint2* Wp, const float* __restrict__ W) {
    int tid = threadIdx.x;
#pragma unroll 1
    for (int idx = tid; idx < 4096; idx += THREADS) {
        int n = idx & 127;
        int rest = idx >> 7;       // 0..31
        int tp = rest & 3;
        int kt = rest >> 2;        // 0..7
        int k0 = kt * 16 + tp * 2;
        uint32_t lo = pack_h2(W[k0 * DIM + n], W[(k0 + 1) * DIM + n]);
        uint32_t hi = pack_h2(W[(k0 + 8) * DIM + n], W[(k0 + 9) * DIM + n]);
        Wp[kt * KTW_H + n * 4 + tp] = make_uint2(lo, hi);
    }
}

// Prefetch: thread owns (row r = tid>>3, k-tile kt = tid&7): 16 consecutive k.
template <bool STREAM>
__device__ __forceinline__ void prefetch_A(float4 v[4], const float* __restrict__ A,
                                           int row0, int M, int tid) {
    int r = tid >> 3, kt = tid & 7;
    int grow = row0 + r;
    if (grow < M) {
        const float4* p = (const float4*)&A[(size_t)grow * DIM + kt * 16];
#pragma unroll
        for (int i = 0; i < 4; ++i) v[i] = STREAM ? __ldcs(p + i) : __ldg(p + i);
    } else {
#pragma unroll
        for (int i = 0; i < 4; ++i) v[i] = make_float4(0.f, 0.f, 0.f, 0.f);
    }
}

// Store to fragment layout: Ap[kt*KTA_H + r*4 + t] =
//   uint2{ h2(k=2t,2t+1), h2(k=8+2t,9+2t) }  (k local to this k-tile)
__device__ __forceinline__ void store_A(uint2* Ap, const float4 v[4], int tid) {
    int r = tid >> 3, kt = tid & 7;
    uint2* base = Ap + kt * KTA_H + r * 4;
    base[0] = make_uint2(pack_h2(v[0].x, v[0].y), pack_h2(v[2].x, v[2].y));
    base[1] = make_uint2(pack_h2(v[0].z, v[0].w), pack_h2(v[2].z, v[2].w));
    base[2] = make_uint2(pack_h2(v[1].x, v[1].y), pack_h2(v[3].x, v[3].y));
    base[3] = make_uint2(pack_h2(v[1].z, v[1].w), pack_h2(v[3].z, v[3].w));
}

// Warp mainloop: 16 rows x 32 cols per warp, K=128 (8 k-tiles of 16)
__device__ __forceinline__ void mma_tile(const uint2* Ap, const uint2* Wp,
                                         int wm, int wn, int lane,
                                         float c[4][4]) {
#pragma unroll
    for (int kt = 0; kt < 8; ++kt) {
        const uint2* ak = Ap + kt * KTA_H;
        const uint2* wk = Wp + kt * KTW_H;
        uint2 aA = ak[wm * 4 + lane];             // (a0, a2): row wm+g
        uint2 aB = ak[(wm + 8) * 4 + lane];       // (a1, a3): row wm+8+g
#pragma unroll
        for (int nf = 0; nf < 4; ++nf) {
            uint2 b = wk[(wn + nf * 8) * 4 + lane];
            mma16(c[nf], aA.x, aB.x, aA.y, aB.y, b.x, b.y);
        }
    }
}

// ---------------------------------------------------------------------------
// Fused node projections: out_w[M,128] = h @ W_w + b_w, fp16 output
// ---------------------------------------------------------------------------
__global__ __launch_bounds__(THREADS, 2)
void gemm_node(const float* __restrict__ A,
               const float* __restrict__ W0, const float* __restrict__ W1,
               const float* __restrict__ W2, const float* __restrict__ B0,
               const float* __restrict__ B1, const float* __restrict__ B2,
               __half* __restrict__ O0, __half* __restrict__ O1,
               __half* __restrict__ O2, int M) {
    extern __shared__ uint2 smem[];
    uint2* Wp = smem;
    uint2* Ap = smem + SMEM_W_U2;
    int which = blockIdx.y;
    const float* W = (which == 0) ? W0 : (which == 1) ? W1 : W2;
    const float* bias = (which == 0) ? B0 : (which == 1) ? B1 : B2;
    __half* out = (which == 0) ? O0 : (which == 1) ? O1 : O2;

    int tid = threadIdx.x, lane = tid & 31, warp = tid >> 5;
    int wm = (warp & 3) * 16, wn = (warp >> 2) * 32;
    int g = lane >> 2, t = lane & 3;

    stage_W(Wp, W);
    float2 bias2[4];
#pragma unroll
    for (int nf = 0; nf < 4; ++nf)
        bias2[nf] = *(const float2*)&bias[wn + nf * 8 + t * 2];

    int nTiles = (M + TILE_M - 1) / TILE_M;
    int tile = blockIdx.x;
    float4 cur[4];
    if (tile < nTiles) prefetch_A<false>(cur, A, tile * TILE_M, M, tid);
    __syncthreads();

#pragma unroll 1
    for (; tile < nTiles; tile += gridDim.x) {
        store_A(Ap, cur, tid);
        __syncthreads();
        int nxt = tile + gridDim.x;
        if (nxt < nTiles) prefetch_A<false>(cur, A, nxt * TILE_M, M, tid);
        float c[4][4];
#pragma unroll
        for (int j = 0; j < 4; ++j)
#pragma unroll
            for (int k = 0; k < 4; ++k) c[j][k] = 0.f;
        mma_tile(Ap, Wp, wm, wn, lane, c);
        __syncthreads();   // A consumed before next store_A
        int r0 = tile * TILE_M + wm + g;
#pragma unroll
        for (int nf = 0; nf < 4; ++nf) {
            int col = wn + nf * 8 + t * 2;
            if (r0 < M)
                *(uint32_t*)&out[(size_t)r0 * DIM + col] =
                    pack_h2(c[nf][0] + bias2[nf].x, c[nf][1] + bias2[nf].y);
            if (r0 + 8 < M)
                *(uint32_t*)&out[(size_t)(r0 + 8) * DIM + col] =
                    pack_h2(c[nf][2] + bias2[nf].x, c[nf][3] + bias2[nf].y);
        }
    }
}

// ---------------------------------------------------------------------------
// Fused edge kernel: proj = e @ We + be, then score/e_out/s/scatter
// ---------------------------------------------------------------------------
__global__ __launch_bounds__(THREADS, 2)
void gemm_edge(const float* __restrict__ Ein, const float* __restrict__ W,
               const float* __restrict__ bias, const int* __restrict__ src,
               const int* __restrict__ dst, float* __restrict__ hacc,
               float* __restrict__ eout) {
    extern __shared__ uint2 smem[];
    uint2* Wp = smem;
    uint2* Ap = smem + SMEM_W_U2;
    __half* Cs = (__half*)(smem + SMEM_W_U2 + SMEM_A_U2);  // dedicated region
    int tid = threadIdx.x, lane = tid & 31, warp = tid >> 5;
    int wm = (warp & 3) * 16, wn = (warp >> 2) * 32;
    int g = lane >> 2, t = lane & 3;

    stage_W(Wp, W);
    float4 be4 = *(const float4*)&bias[lane * 4];

    const int nTiles = N_EDGES / TILE_M;  // 12500 exact
    int tile = blockIdx.x;
    float4 cur[4];
    if (tile < nTiles) prefetch_A<true>(cur, Ein, tile * TILE_M, N_EDGES, tid);
    __syncthreads();

#pragma unroll 1
    for (; tile < nTiles; tile += gridDim.x) {
        store_A(Ap, cur, tid);
        __syncthreads();                       // A published; prev Cs reads done
        float c[4][4];
#pragma unroll
        for (int j = 0; j < 4; ++j)
#pragma unroll
            for (int k = 0; k < 4; ++k) c[j][k] = 0.f;
        mma_tile(Ap, Wp, wm, wn, lane, c);
        // prefetch next tile: overlaps Cs-write + gather/scatter epilogue
        int nxt = tile + gridDim.x;
        if (nxt < nTiles) prefetch_A<true>(cur, Ein, nxt * TILE_M, N_EDGES, tid);
        // write own fragment rows to Cs (fp16, own region; no pre-sync needed)
        {
            int rr = wm + g;
#pragma unroll
            for (int nf = 0; nf < 4; ++nf) {
                int col = wn + nf * 8 + t * 2;
                *(uint32_t*)&Cs[rr * CS_H_STRIDE + col] =
                    pack_h2(c[nf][0], c[nf][1]);
                *(uint32_t*)&Cs[(rr + 8) * CS_H_STRIDE + col] =
                    pack_h2(c[nf][2], c[nf][3]);
            }
        }
        __syncthreads();                       // Cs published; all mma done

        // epilogue: each warp owns 4 edges; 2 at a time, loads batched
        int rbase = warp * 4;
        int ebase = tile * TILE_M + rbase;
        int sn[4], dn[4];
#pragma unroll
        for (int i = 0; i < 4; ++i) {
            sn[i] = __ldg(&src[ebase + i]);
            dn[i] = __ldg(&dst[ebase + i]);
        }
#pragma unroll
        for (int i = 0; i < 4; i += 2) {
            // batch all gathers for both edges first (uint2 = 4 halves/lane)
            uint2 qr0 = *(const uint2*)&g_Q[(size_t)dn[i] * DIM + lane * 4];
            uint2 kr0 = *(const uint2*)&g_K[(size_t)sn[i] * DIM + lane * 4];
            uint2 vr0 = *(const uint2*)&g_V[(size_t)sn[i] * DIM + lane * 4];
            uint2 qr1 = *(const uint2*)&g_Q[(size_t)dn[i + 1] * DIM + lane * 4];
            uint2 kr1 = *(const uint2*)&g_K[(size_t)sn[i + 1] * DIM + lane * 4];
            uint2 vr1 = *(const uint2*)&g_V[(size_t)sn[i + 1] * DIM + lane * 4];
            uint2 w0 = *(const uint2*)&Cs[(rbase + i) * CS_H_STRIDE + lane * 4];
            uint2 w1 = *(const uint2*)&Cs[(rbase + i + 1) * CS_H_STRIDE + lane * 4];

            float4 q0 = unpack_h4(qr0), k0 = unpack_h4(kr0), v0 = unpack_h4(vr0);
            float4 q1 = unpack_h4(qr1), k1 = unpack_h4(kr1), v1 = unpack_h4(vr1);
            float4 c0 = unpack_h4(w0), c1 = unpack_h4(w1);
            float4 p0 = make_float4(c0.x + be4.x, c0.y + be4.y,
                                    c0.z + be4.z, c0.w + be4.w);
            float4 p1 = make_float4(c1.x + be4.x, c1.y + be4.y,
                                    c1.z + be4.z, c1.w + be4.w);

            float4 s0, s1;
            s0.x = q0.x * k0.x * 0.25f * p0.x;
            s0.y = q0.y * k0.y * 0.25f * p0.y;
            s0.z = q0.z * k0.z * 0.25f * p0.z;
            s0.w = q0.w * k0.w * 0.25f * p0.w;
            s1.x = q1.x * k1.x * 0.25f * p1.x;
            s1.y = q1.y * k1.y * 0.25f * p1.y;
            s1.z = q1.z * k1.z * 0.25f * p1.z;
            s1.w = q1.w * k1.w * 0.25f * p1.w;
            __stcs((float4*)&eout[(size_t)(ebase + i) * DIM + lane * 4], s0);
            __stcs((float4*)&eout[(size_t)(ebase + i + 1) * DIM + lane * 4], s1);

            float h0 = s0.x + s0.y + s0.z + s0.w;
            float h1 = s1.x + s1.y + s1.z + s1.w;
            h0 += __shfl_xor_sync(0xffffffffu, h0, 1);
            h0 += __shfl_xor_sync(0xffffffffu, h0, 2);
            h1 += __shfl_xor_sync(0xffffffffu, h1, 1);
            h1 += __shfl_xor_sync(0xffffffffu, h1, 2);
            float e0 = expf(fminf(fmaxf(h0, -5.f), 5.f));
            float e1 = expf(fminf(fmaxf(h1, -5.f), 5.f));

            red_add_v4(&hacc[(size_t)dn[i] * DIM + lane * 4],
                       make_float4(v0.x * e0, v0.y * e0, v0.z * e0, v0.w * e0));
            red_add_v4(&hacc[(size_t)dn[i + 1] * DIM + lane * 4],
                       make_float4(v1.x * e1, v1.y * e1, v1.z * e1, v1.w * e1));
            if ((lane & 3) == 0) {
                red_add_f32(&g_z[dn[i] * HEADS + (lane >> 2)], e0);
                red_add_f32(&g_z[dn[i + 1] * HEADS + (lane >> 2)], e1);
            }
        }
        // no sync: next iteration's post-store_A sync orders Cs reuse
    }
}

// ---------------------------------------------------------------------------
// finalize: h_out = wV / (z + 1e-6)
// ---------------------------------------------------------------------------
__global__ void finalize_kernel(float* __restrict__ hacc) {
    int i = blockIdx.x * blockDim.x + threadIdx.x;
    if (i < N_NODES * DIM) {
        int node = i >> 7;
        int head = (i >> 4) & 7;
        hacc[i] = hacc[i] / (g_z[node * HEADS + head] + 1e-6f);
    }
}

// ---------------------------------------------------------------------------
// launch
// ---------------------------------------------------------------------------
extern "C" void kernel_launch(void* const* d_in, const int* in_sizes, int n_in,
                              void* d_out, int out_size) {
    const float* h  = (const float*)d_in[0];
    const float* e  = (const float*)d_in[1];
    const int*   src = (const int*)d_in[2];
    const int*   dst = (const int*)d_in[3];
    const float* Wq = (const float*)d_in[4];
    const float* bq = (const float*)d_in[5];
    const float* Wk = (const float*)d_in[6];
    const float* bk = (const float*)d_in[7];
    const float* Wv = (const float*)d_in[8];
    const float* bv = (const float*)d_in[9];
    const float* We = (const float*)d_in[10];
    const float* be = (const float*)d_in[11];

    float* out  = (float*)d_out;
    float* hacc = out;                               // [N,H,D] accumulator -> h_out
    float* eout = out + (size_t)N_NODES * DIM;       // [E,H,D] e_out

    __half *qp, *kp, *vp;
    float *zp;
    cudaGetSymbolAddress((void**)&qp, g_Q);
    cudaGetSymbolAddress((void**)&kp, g_K);
    cudaGetSymbolAddress((void**)&vp, g_V);
    cudaGetSymbolAddress((void**)&zp, g_z);

    cudaFuncSetAttribute(gemm_node, cudaFuncAttributeMaxDynamicSharedMemorySize, NODE_SMEM);
    cudaFuncSetAttribute(gemm_edge, cudaFuncAttributeMaxDynamicSharedMemorySize, EDGE_SMEM);

    cudaMemsetAsync(hacc, 0, (size_t)N_NODES * DIM * sizeof(float));
    cudaMemsetAsync(zp, 0, (size_t)N_NODES * HEADS * sizeof(float));

    dim3 ngrid(GRID, 3);
    gemm_node<<<ngrid, THREADS, NODE_SMEM>>>(h, Wq, Wk, Wv, bq, bk, bv,
                                             qp, kp, vp, N_NODES);
    gemm_edge<<<GRID, THREADS, EDGE_SMEM>>>(e, We, be, src, dst, hacc, eout);
    finalize_kernel<<<(N_NODES * DIM + 255) / 256, 256>>>(hacc);
}

// round 15
// speedup vs baseline: 1.4106x; 1.0140x over previous
#include <cuda_runtime.h>
#include <cuda_fp16.h>
#include <cstdint>

#define N_NODES 50000
#define N_EDGES 800000
#define DIM 128
#define HEADS 8
#define TILE_M 64
#define THREADS 512
#define KTW_H 517                 // uint2 per k-tile for W (128 n * 4 + 5 pad)
#define KTA_H 261                 // uint2 per k-tile for A (64 rows * 4 + 5 pad)
#define CS_H_STRIDE 136           // halves per Cs row (272 B, 8B-aligned lane reads)
#define SMEM_W_U2 (8 * KTW_H)     // 4136 uint2 = 33088 B
#define SMEM_A_U2 (8 * KTA_H)     // 2088 uint2 = 16704 B
#define NODE_SMEM ((SMEM_W_U2 + SMEM_A_U2) * 8)             // 49792 B
#define EDGE_SMEM (NODE_SMEM + TILE_M * CS_H_STRIDE * 2)    // 67200 B -> 2 CTAs/SM
#define GRID 296

// Scratch (allocation-free rule: __device__ globals) — fp16 halves gather bytes
__device__ __half g_Q[N_NODES * DIM];
__device__ __half g_K[N_NODES * DIM];
__device__ __half g_V[N_NODES * DIM];
__device__ float  g_z[N_NODES * HEADS];

// ---------------------------------------------------------------------------
// helpers
// ---------------------------------------------------------------------------
__device__ __forceinline__ uint32_t pack_h2(float lo, float hi) {
    __half2 h = __floats2half2_rn(lo, hi);   // .x -> low 16 bits
    return *reinterpret_cast<uint32_t*>(&h);
}

__device__ __forceinline__ float4 unpack_h4(uint2 w) {
    float2 a = __half22float2(*reinterpret_cast<__half2*>(&w.x));
    float2 b = __half22float2(*reinterpret_cast<__half2*>(&w.y));
    return make_float4(a.x, a.y, b.x, b.y);
}

// m16n8k16 f16 mma, f32 accumulate.
__device__ __forceinline__ void mma16(float c[4], uint32_t a0, uint32_t a1,
                                      uint32_t a2, uint32_t a3,
                                      uint32_t b0, uint32_t b1) {
    asm("mma.sync.aligned.m16n8k16.row.col.f32.f16.f16.f32 "
        "{%0,%1,%2,%3}, {%4,%5,%6,%7}, {%8,%9}, {%0,%1,%2,%3};\n"
        : "+f"(c[0]), "+f"(c[1]), "+f"(c[2]), "+f"(c[3])
        : "r"(a0), "r"(a1), "r"(a2), "r"(a3), "r"(b0), "r"(b1));
}

__device__ __forceinline__ void red_add_v4(float* p, float4 v) {
    asm volatile("red.global.add.v4.f32 [%0], {%1,%2,%3,%4};"
                 :: "l"(p), "f"(v.x), "f"(v.y), "f"(v.z), "f"(v.w));
}

__device__ __forceinline__ void red_add_f32(float* p, float v) {
    asm volatile("red.global.add.f32 [%0], %1;" :: "l"(p), "f"(v));
}

// Stage W[128][128] (row-major k x n) into fp16 fragment layout.
__device__ __forceinline__ void stage_W(uint2* Wp, const float* __restrict__ W) {
    int tid = threadIdx.x;
#pragma unroll 1
    for (int idx = tid; idx < 4096; idx += THREADS) {
        int n = idx & 127;
        int rest = idx >> 7;       // 0..31
        int tp = rest & 3;
        int kt = rest >> 2;        // 0..7
        int k0 = kt * 16 + tp * 2;
        uint32_t lo = pack_h2(W[k0 * DIM + n], W[(k0 + 1) * DIM + n]);
        uint32_t hi = pack_h2(W[(k0 + 8) * DIM + n], W[(k0 + 9) * DIM + n]);
        Wp[kt * KTW_H + n * 4 + tp] = make_uint2(lo, hi);
    }
}

// Prefetch: thread owns (row r = tid>>3, k-tile kt = tid&7): 16 consecutive k.
template <bool STREAM>
__device__ __forceinline__ void prefetch_A(float4 v[4], const float* __restrict__ A,
                                           int row0, int M, int tid) {
    int r = tid >> 3, kt = tid & 7;
    int grow = row0 + r;
    if (grow < M) {
        const float4* p = (const float4*)&A[(size_t)grow * DIM + kt * 16];
#pragma unroll
        for (int i = 0; i < 4; ++i) v[i] = STREAM ? __ldcs(p + i) : __ldg(p + i);
    } else {
#pragma unroll
        for (int i = 0; i < 4; ++i) v[i] = make_float4(0.f, 0.f, 0.f, 0.f);
    }
}

// Store to fragment layout: Ap[kt*KTA_H + r*4 + t] =
//   uint2{ h2(k=2t,2t+1), h2(k=8+2t,9+2t) }  (k local to this k-tile)
__device__ __forceinline__ void store_A(uint2* Ap, const float4 v[4], int tid) {
    int r = tid >> 3, kt = tid & 7;
    uint2* base = Ap + kt * KTA_H + r * 4;
    base[0] = make_uint2(pack_h2(v[0].x, v[0].y), pack_h2(v[2].x, v[2].y));
    base[1] = make_uint2(pack_h2(v[0].z, v[0].w), pack_h2(v[2].z, v[2].w));
    base[2] = make_uint2(pack_h2(v[1].x, v[1].y), pack_h2(v[3].x, v[3].y));
    base[3] = make_uint2(pack_h2(v[1].z, v[1].w), pack_h2(v[3].z, v[3].w));
}

// Warp mainloop: 16 rows x 32 cols per warp, K=128 (8 k-tiles of 16)
__device__ __forceinline__ void mma_tile(const uint2* Ap, const uint2* Wp,
                                         int wm, int wn, int lane,
                                         float c[4][4]) {
#pragma unroll
    for (int kt = 0; kt < 8; ++kt) {
        const uint2* ak = Ap + kt * KTA_H;
        const uint2* wk = Wp + kt * KTW_H;
        uint2 aA = ak[wm * 4 + lane];             // (a0, a2): row wm+g
        uint2 aB = ak[(wm + 8) * 4 + lane];       // (a1, a3): row wm+8+g
#pragma unroll
        for (int nf = 0; nf < 4; ++nf) {
            uint2 b = wk[(wn + nf * 8) * 4 + lane];
            mma16(c[nf], aA.x, aB.x, aA.y, aB.y, b.x, b.y);
        }
    }
}

// ---------------------------------------------------------------------------
// Fused node projections: out_w[M,128] = h @ W_w + b_w, fp16 output
// ---------------------------------------------------------------------------
__global__ __launch_bounds__(THREADS, 2)
void gemm_node(const float* __restrict__ A,
               const float* __restrict__ W0, const float* __restrict__ W1,
               const float* __restrict__ W2, const float* __restrict__ B0,
               const float* __restrict__ B1, const float* __restrict__ B2,
               __half* __restrict__ O0, __half* __restrict__ O1,
               __half* __restrict__ O2, int M) {
    extern __shared__ uint2 smem[];
    uint2* Wp = smem;
    uint2* Ap = smem + SMEM_W_U2;
    int which = blockIdx.y;
    const float* W = (which == 0) ? W0 : (which == 1) ? W1 : W2;
    const float* bias = (which == 0) ? B0 : (which == 1) ? B1 : B2;
    __half* out = (which == 0) ? O0 : (which == 1) ? O1 : O2;

    int tid = threadIdx.x, lane = tid & 31, warp = tid >> 5;
    int wm = (warp & 3) * 16, wn = (warp >> 2) * 32;
    int g = lane >> 2, t = lane & 3;

    stage_W(Wp, W);
    float2 bias2[4];
#pragma unroll
    for (int nf = 0; nf < 4; ++nf)
        bias2[nf] = *(const float2*)&bias[wn + nf * 8 + t * 2];

    int nTiles = (M + TILE_M - 1) / TILE_M;
    int tile = blockIdx.x;
    float4 cur[4];
    if (tile < nTiles) prefetch_A<false>(cur, A, tile * TILE_M, M, tid);
    __syncthreads();

#pragma unroll 1
    for (; tile < nTiles; tile += gridDim.x) {
        store_A(Ap, cur, tid);
        __syncthreads();
        int nxt = tile + gridDim.x;
        if (nxt < nTiles) prefetch_A<false>(cur, A, nxt * TILE_M, M, tid);
        float c[4][4];
#pragma unroll
        for (int j = 0; j < 4; ++j)
#pragma unroll
            for (int k = 0; k < 4; ++k) c[j][k] = 0.f;
        mma_tile(Ap, Wp, wm, wn, lane, c);
        __syncthreads();   // A consumed before next store_A
        int r0 = tile * TILE_M + wm + g;
#pragma unroll
        for (int nf = 0; nf < 4; ++nf) {
            int col = wn + nf * 8 + t * 2;
            if (r0 < M)
                *(uint32_t*)&out[(size_t)r0 * DIM + col] =
                    pack_h2(c[nf][0] + bias2[nf].x, c[nf][1] + bias2[nf].y);
            if (r0 + 8 < M)
                *(uint32_t*)&out[(size_t)(r0 + 8) * DIM + col] =
                    pack_h2(c[nf][2] + bias2[nf].x, c[nf][3] + bias2[nf].y);
        }
    }
}

// ---------------------------------------------------------------------------
// Fused edge kernel: proj = e @ We + be, then score/e_out/s/scatter
// ---------------------------------------------------------------------------
__global__ __launch_bounds__(THREADS, 2)
void gemm_edge(const float* __restrict__ Ein, const float* __restrict__ W,
               const float* __restrict__ bias, const int* __restrict__ src,
               const int* __restrict__ dst, float* __restrict__ hacc,
               float* __restrict__ eout) {
    extern __shared__ uint2 smem[];
    uint2* Wp = smem;
    uint2* Ap = smem + SMEM_W_U2;
    __half* Cs = (__half*)(smem + SMEM_W_U2 + SMEM_A_U2);  // dedicated region
    int tid = threadIdx.x, lane = tid & 31, warp = tid >> 5;
    int wm = (warp & 3) * 16, wn = (warp >> 2) * 32;
    int g = lane >> 2, t = lane & 3;

    stage_W(Wp, W);
    float4 be4 = *(const float4*)&bias[lane * 4];

    const int nTiles = N_EDGES / TILE_M;  // 12500 exact
    int tile = blockIdx.x;
    float4 cur[4];
    if (tile < nTiles) prefetch_A<true>(cur, Ein, tile * TILE_M, N_EDGES, tid);
    __syncthreads();

#pragma unroll 1
    for (; tile < nTiles; tile += gridDim.x) {
        store_A(Ap, cur, tid);
        __syncthreads();                       // A published; prev Cs reads done
        float c[4][4];
#pragma unroll
        for (int j = 0; j < 4; ++j)
#pragma unroll
            for (int k = 0; k < 4; ++k) c[j][k] = 0.f;
        mma_tile(Ap, Wp, wm, wn, lane, c);
        // prefetch next tile: overlaps Cs-write + gather/scatter epilogue
        int nxt = tile + gridDim.x;
        if (nxt < nTiles) prefetch_A<true>(cur, Ein, nxt * TILE_M, N_EDGES, tid);
        // write own fragment rows to Cs (fp16, own region; no pre-sync needed)
        {
            int rr = wm + g;
#pragma unroll
            for (int nf = 0; nf < 4; ++nf) {
                int col = wn + nf * 8 + t * 2;
                *(uint32_t*)&Cs[rr * CS_H_STRIDE + col] =
                    pack_h2(c[nf][0], c[nf][1]);
                *(uint32_t*)&Cs[(rr + 8) * CS_H_STRIDE + col] =
                    pack_h2(c[nf][2], c[nf][3]);
            }
        }
        __syncthreads();                       // Cs published; all mma done

        // epilogue: each warp owns 4 edges; 2 at a time, loads batched
        int rbase = warp * 4;
        int ebase = tile * TILE_M + rbase;
        int sn[4], dn[4];
#pragma unroll
        for (int i = 0; i < 4; ++i) {
            sn[i] = __ldg(&src[ebase + i]);
            dn[i] = __ldg(&dst[ebase + i]);
        }
#pragma unroll
        for (int i = 0; i < 4; i += 2) {
            // batch all gathers for both edges first (uint2 = 4 halves/lane)
            uint2 qr0 = *(const uint2*)&g_Q[(size_t)dn[i] * DIM + lane * 4];
            uint2 kr0 = *(const uint2*)&g_K[(size_t)sn[i] * DIM + lane * 4];
            uint2 vr0 = *(const uint2*)&g_V[(size_t)sn[i] * DIM + lane * 4];
            uint2 qr1 = *(const uint2*)&g_Q[(size_t)dn[i + 1] * DIM + lane * 4];
            uint2 kr1 = *(const uint2*)&g_K[(size_t)sn[i + 1] * DIM + lane * 4];
            uint2 vr1 = *(const uint2*)&g_V[(size_t)sn[i + 1] * DIM + lane * 4];
            uint2 w0 = *(const uint2*)&Cs[(rbase + i) * CS_H_STRIDE + lane * 4];
            uint2 w1 = *(const uint2*)&Cs[(rbase + i + 1) * CS_H_STRIDE + lane * 4];

            float4 q0 = unpack_h4(qr0), k0 = unpack_h4(kr0), v0 = unpack_h4(vr0);
            float4 q1 = unpack_h4(qr1), k1 = unpack_h4(kr1), v1 = unpack_h4(vr1);
            float4 c0 = unpack_h4(w0), c1 = unpack_h4(w1);
            float4 p0 = make_float4(c0.x + be4.x, c0.y + be4.y,
                                    c0.z + be4.z, c0.w + be4.w);
            float4 p1 = make_float4(c1.x + be4.x, c1.y + be4.y,
                                    c1.z + be4.z, c1.w + be4.w);

            float4 s0, s1;
            s0.x = q0.x * k0.x * 0.25f * p0.x;
            s0.y = q0.y * k0.y * 0.25f * p0.y;
            s0.z = q0.z * k0.z * 0.25f * p0.z;
            s0.w = q0.w * k0.w * 0.25f * p0.w;
            s1.x = q1.x * k1.x * 0.25f * p1.x;
            s1.y = q1.y * k1.y * 0.25f * p1.y;
            s1.z = q1.z * k1.z * 0.25f * p1.z;
            s1.w = q1.w * k1.w * 0.25f * p1.w;
            __stcs((float4*)&eout[(size_t)(ebase + i) * DIM + lane * 4], s0);
            __stcs((float4*)&eout[(size_t)(ebase + i + 1) * DIM + lane * 4], s1);

            float h0 = s0.x + s0.y + s0.z + s0.w;
            float h1 = s1.x + s1.y + s1.z + s1.w;
            h0 += __shfl_xor_sync(0xffffffffu, h0, 1);
            h0 += __shfl_xor_sync(0xffffffffu, h0, 2);
            h1 += __shfl_xor_sync(0xffffffffu, h1, 1);
            h1 += __shfl_xor_sync(0xffffffffu, h1, 2);
            // fast exp: clamped input |x|<=5, __expf error ~1e-6 << 6e-4 budget
            float e0 = __expf(fminf(fmaxf(h0, -5.f), 5.f));
            float e1 = __expf(fminf(fmaxf(h1, -5.f), 5.f));

            red_add_v4(&hacc[(size_t)dn[i] * DIM + lane * 4],
                       make_float4(v0.x * e0, v0.y * e0, v0.z * e0, v0.w * e0));
            red_add_v4(&hacc[(size_t)dn[i + 1] * DIM + lane * 4],
                       make_float4(v1.x * e1, v1.y * e1, v1.z * e1, v1.w * e1));
            if ((lane & 3) == 0) {
                red_add_f32(&g_z[dn[i] * HEADS + (lane >> 2)], e0);
                red_add_f32(&g_z[dn[i + 1] * HEADS + (lane >> 2)], e1);
            }
        }
        // no sync: next iteration's post-store_A sync orders Cs reuse
    }
}

// ---------------------------------------------------------------------------
// finalize: h_out = wV / (z + 1e-6)
// ---------------------------------------------------------------------------
__global__ void finalize_kernel(float* __restrict__ hacc) {
    int i = blockIdx.x * blockDim.x + threadIdx.x;
    if (i < N_NODES * DIM) {
        int node = i >> 7;
        int head = (i >> 4) & 7;
        hacc[i] = hacc[i] / (g_z[node * HEADS + head] + 1e-6f);
    }
}

// ---------------------------------------------------------------------------
// launch
// ---------------------------------------------------------------------------
extern "C" void kernel_launch(void* const* d_in, const int* in_sizes, int n_in,
                              void* d_out, int out_size) {
    const float* h  = (const float*)d_in[0];
    const float* e  = (const float*)d_in[1];
    const int*   src = (const int*)d_in[2];
    const int*   dst = (const int*)d_in[3];
    const float* Wq = (const float*)d_in[4];
    const float* bq = (const float*)d_in[5];
    const float* Wk = (const float*)d_in[6];
    const float* bk = (const float*)d_in[7];
    const float* Wv = (const float*)d_in[8];
    const float* bv = (const float*)d_in[9];
    const float* We = (const float*)d_in[10];
    const float* be = (const float*)d_in[11];

    float* out  = (float*)d_out;
    float* hacc = out;                               // [N,H,D] accumulator -> h_out
    float* eout = out + (size_t)N_NODES * DIM;       // [E,H,D] e_out

    __half *qp, *kp, *vp;
    float *zp;
    cudaGetSymbolAddress((void**)&qp, g_Q);
    cudaGetSymbolAddress((void**)&kp, g_K);
    cudaGetSymbolAddress((void**)&vp, g_V);
    cudaGetSymbolAddress((void**)&zp, g_z);

    cudaFuncSetAttribute(gemm_node, cudaFuncAttributeMaxDynamicSharedMemorySize, NODE_SMEM);
    cudaFuncSetAttribute(gemm_edge, cudaFuncAttributeMaxDynamicSharedMemorySize, EDGE_SMEM);

    cudaMemsetAsync(hacc, 0, (size_t)N_NODES * DIM * sizeof(float));
    cudaMemsetAsync(zp, 0, (size_t)N_NODES * HEADS * sizeof(float));

    dim3 ngrid(GRID, 3);
    gemm_node<<<ngrid, THREADS, NODE_SMEM>>>(h, Wq, Wk, Wv, bq, bk, bv,
                                             qp, kp, vp, N_NODES);
    gemm_edge<<<GRID, THREADS, EDGE_SMEM>>>(e, We, be, src, dst, hacc, eout);
    finalize_kernel<<<(N_NODES * DIM + 255) / 256, 256>>>(hacc);
}